// round 3
// baseline (speedup 1.0000x reference)
#include <cuda_runtime.h>
#include <stdint.h>

// Problem: B x N fp32 scores. Outputs (concatenated into float d_out):
//   [0, B*N)      portfolio_weights (sparse +softmax(top20), -softmax(bot20))
//   [B*N, 2*B*N)  sorted_indices of argsort(-scores) as float
#define N_COLS 8192
#define NB     4096   // buckets per row
#define NT     1024   // threads per CTA (one CTA per row)

// Monotone value->bucket table, indexed by top 16 bits of descending sort key.
__device__ unsigned short g_bucket_tab[65536];

// ---------------------------------------------------------------------------
// Build bucket table from normal CDF (equal-probability buckets for N(0,1)).
// dkey = ~sortable(x); ascending dkey == descending x. Table must be monotone
// non-decreasing in the 16-bit prefix; fix_table enforces that exactly.
// ---------------------------------------------------------------------------
__global__ void pg_build_table_kernel() {
    int j = blockIdx.x * blockDim.x + threadIdx.x;   // 0..65535
    unsigned int dkey = ((unsigned int)j) << 16;
    unsigned int ukey = ~dkey;
    float x;
    if (ukey & 0x80000000u) x = __uint_as_float(ukey ^ 0x80000000u);
    else                    x = __uint_as_float(~ukey);
    int b;
    if (!(x == x)) {
        // NaN prefixes: top of ukey range = largest x side -> bucket 0
        b = (ukey & 0x80000000u) ? 0 : (NB - 1);
    } else {
        float xc = fminf(fmaxf(x, -30.0f), 30.0f);
        float q = normcdff(-xc);                     // = 1 - CDF(x), monotone dec. in x
        int bb = (int)floorf(q * (float)NB);
        b = bb < 0 ? 0 : (bb > NB - 1 ? NB - 1 : bb);
    }
    g_bucket_tab[j] = (unsigned short)b;
}

// Enforce monotone non-decreasing table via block-wide running max.
__global__ void pg_fix_table_kernel() {
    __shared__ int tmax[NT];
    int t = threadIdx.x;
    int base = t * 64;
    int cm = 0;
    for (int i = 0; i < 64; i++) cm = max(cm, (int)g_bucket_tab[base + i]);
    tmax[t] = cm;
    __syncthreads();
    for (int d = 1; d < NT; d <<= 1) {
        int v = (t >= d) ? tmax[t - d] : 0;
        __syncthreads();
        if (t >= d) tmax[t] = max(tmax[t], v);
        __syncthreads();
    }
    int run = (t == 0) ? 0 : tmax[t - 1];   // exclusive prefix max
    for (int i = 0; i < 64; i++) {
        int v = (int)g_bucket_tab[base + i];
        run = max(run, v);
        g_bucket_tab[base + i] = (unsigned short)run;
    }
}

// ---------------------------------------------------------------------------
// Main kernel: one CTA per row.
// Phase 1: load row, compute dkey, histogram into 4096 shared buckets.
// Phase 2: block exclusive scan of bucket counts.
// Phase 3: scatter packed (dkey|idx) u64 into bucket-contiguous shared array.
// Phase 4: per-bucket insertion sort (buckets are tiny by CDF design).
// Phase 5: write sorted indices; zero weights row; softmax top/bot 20.
// ---------------------------------------------------------------------------
__global__ void __launch_bounds__(NT)
pg_sort_kernel(const float* __restrict__ in, float* __restrict__ out,
               int B, int write_indices) {
    extern __shared__ unsigned char smem_raw[];
    unsigned long long* data = (unsigned long long*)smem_raw;                 // 8192 * 8
    unsigned int* offs = (unsigned int*)(smem_raw + 8192 * 8);                // 4096 * 4
    unsigned int* wsum = (unsigned int*)(smem_raw + 8192 * 8 + 4096 * 4);     // 32  * 4
    float* sc_val = (float*)(smem_raw + 8192 * 8 + 4096 * 4 + 128);           // 40 floats
    int*   sc_idx = (int*)  (smem_raw + 8192 * 8 + 4096 * 4 + 128 + 160);     // 40 ints

    int row = blockIdx.x;
    int tid = threadIdx.x;
    const float* rowp = in + (size_t)row * N_COLS;
    const float4* rowp4 = (const float4*)rowp;

    // zero histogram
    for (int j = tid; j < NB; j += NT) offs[j] = 0;
    __syncthreads();

    // load 8 values/thread, compute descending sort keys, histogram
    float4 v0 = rowp4[tid];
    float4 v1 = rowp4[tid + NT];
    unsigned int dk[8];
    {
        float vv[8] = {v0.x, v0.y, v0.z, v0.w, v1.x, v1.y, v1.z, v1.w};
#pragma unroll
        for (int k = 0; k < 8; k++) {
            unsigned int u = __float_as_uint(vv[k]);
            unsigned int ukey = (u & 0x80000000u) ? ~u : (u | 0x80000000u);
            dk[k] = ~ukey;   // ascending dk == descending value
        }
    }
#pragma unroll
    for (int k = 0; k < 8; k++) {
        int b = (int)g_bucket_tab[dk[k] >> 16];
        atomicAdd(&offs[b], 1u);
    }
    __syncthreads();

    // exclusive scan of 4096 counts (4 bins/thread)
    {
        int j0 = tid * 4;
        unsigned int c0 = offs[j0], c1 = offs[j0 + 1], c2 = offs[j0 + 2], c3 = offs[j0 + 3];
        unsigned int s = c0 + c1 + c2 + c3;
        unsigned int inc = s;
#pragma unroll
        for (int d = 1; d < 32; d <<= 1) {
            unsigned int v = __shfl_up_sync(0xFFFFFFFFu, inc, d);
            if ((tid & 31) >= d) inc += v;
        }
        if ((tid & 31) == 31) wsum[tid >> 5] = inc;
        __syncthreads();
        if (tid < 32) {
            unsigned int w = wsum[tid];
            unsigned int wi = w;
#pragma unroll
            for (int d = 1; d < 32; d <<= 1) {
                unsigned int v = __shfl_up_sync(0xFFFFFFFFu, wi, d);
                if (tid >= d) wi += v;
            }
            wsum[tid] = wi - w;  // exclusive warp offsets
        }
        __syncthreads();
        unsigned int excl = inc - s + wsum[tid >> 5];
        offs[j0]     = excl;
        offs[j0 + 1] = excl + c0;
        offs[j0 + 2] = excl + c0 + c1;
        offs[j0 + 3] = excl + c0 + c1 + c2;
    }
    __syncthreads();

    // scatter packed key|idx; offs[b] becomes END offset of bucket b afterwards
#pragma unroll
    for (int k = 0; k < 8; k++) {
        int b = (int)g_bucket_tab[dk[k] >> 16];
        unsigned int pos = atomicAdd(&offs[b], 1u);
        int idx = (k < 4) ? (4 * tid + k) : (4 * (tid + NT) + (k - 4));
        data[pos] = ((unsigned long long)dk[k] << 32) | (unsigned int)idx;
    }
    __syncthreads();

    // per-bucket insertion sort (ascending u64 -> descending value, ties by idx asc)
    for (int b = tid; b < NB; b += NT) {
        int end = (int)offs[b];
        int start = (b == 0) ? 0 : (int)offs[b - 1];
        for (int i = start + 1; i < end; i++) {
            unsigned long long v = data[i];
            int k = i - 1;
            while (k >= start && data[k] > v) { data[k + 1] = data[k]; k--; }
            data[k + 1] = v;
        }
    }
    __syncthreads();

    // write sorted_indices as float (coalesced float4)
    if (write_indices) {
        float4* oidx4 = (float4*)(out + (size_t)B * N_COLS + (size_t)row * N_COLS);
#pragma unroll
        for (int g = 0; g < 2; g++) {
            int base = 4 * (tid + g * NT);
            float4 f;
            f.x = (float)(unsigned int)(data[base + 0] & 0xFFFFFFFFull);
            f.y = (float)(unsigned int)(data[base + 1] & 0xFFFFFFFFull);
            f.z = (float)(unsigned int)(data[base + 2] & 0xFFFFFFFFull);
            f.w = (float)(unsigned int)(data[base + 3] & 0xFFFFFFFFull);
            oidx4[tid + g * NT] = f;
        }
    }

    // zero portfolio_weights row
    float* ow = out + (size_t)row * N_COLS;
    float4* ow4 = (float4*)ow;
    float4 z = make_float4(0.f, 0.f, 0.f, 0.f);
    ow4[tid] = z;
    ow4[tid + NT] = z;

    // gather top-20 / bottom-20 scores
    if (tid < 20) {
        int idx = (int)(data[tid] & 0xFFFFFFFFull);
        sc_idx[tid] = idx;
        sc_val[tid] = rowp[idx];
    } else if (tid < 40) {
        int k = tid - 20;
        int idx = (int)(data[N_COLS - 20 + k] & 0xFFFFFFFFull);
        sc_idx[tid] = idx;
        sc_val[tid] = -rowp[idx];   // bot_scores = -score
    }
    __syncthreads();  // also orders the zero-fill stores before the scatter below

    if (tid < 40) {
        int g0 = (tid < 20) ? 0 : 20;
        float m = -1e30f;
#pragma unroll
        for (int j = 0; j < 20; j++) m = fmaxf(m, sc_val[g0 + j]);
        float s = 0.f;
#pragma unroll
        for (int j = 0; j < 20; j++) s += expf(sc_val[g0 + j] - m);
        float w = expf(sc_val[tid] - m) / s;
        ow[sc_idx[tid]] = (tid < 20) ? w : -w;
    }
}

extern "C" void kernel_launch(void* const* d_in, const int* in_sizes, int n_in,
                              void* d_out, int out_size) {
    const float* in = (const float*)d_in[0];
    float* out = (float*)d_out;
    int total = in_sizes[0];
    int B = total / N_COLS;
    int write_indices = (out_size >= 2 * total) ? 1 : 0;

    const int smem_bytes = 8192 * 8 + 4096 * 4 + 128 + 160 + 160;  // 82368
    cudaFuncSetAttribute(pg_sort_kernel,
                         cudaFuncAttributeMaxDynamicSharedMemorySize, smem_bytes);

    pg_build_table_kernel<<<64, 1024>>>();
    pg_fix_table_kernel<<<1, NT>>>();
    pg_sort_kernel<<<B, NT, smem_bytes>>>(in, out, B, write_indices);
}